// round 7
// baseline (speedup 1.0000x reference)
#include <cuda_runtime.h>
#include <cstdint>
#include <cstddef>

// Problem dims (fixed by reference)
#define Bb 256
#define Tt 512
#define Dd 64
#define Ll 32
#define Hh 128
#define G4 512   // 4*H

// ---------------- scratch (device globals; no allocation allowed) ----------
__device__ float g_pre[(size_t)Bb * Tt * G4];   // 268 MB: pre-activations

// ---------------- math helpers ---------------------------------------------
__device__ __forceinline__ float sigf(float x) {
    return __fdividef(1.0f, 1.0f + __expf(-x));
}
__device__ __forceinline__ float tanhf_fast(float x) {
    x = fminf(20.0f, fmaxf(-20.0f, x));
    float e = __expf(-2.0f * x);
    return __fdividef(1.0f - e, 1.0f + e);
}

// ============================================================================
// Kernel 1: pre-GEMM with fused static part (R5 body, unchanged — proven).
// ============================================================================
#define PRE_MT 64
#define PRE_NT 128
#define PRE_PAD 65
#define PRE_SMEM (((PRE_MT + PRE_NT) * PRE_PAD + PRE_NT) * 4)   // 50432 bytes

__global__ __launch_bounds__(256) void pre_kernel(
    const float* __restrict__ xd, const float* __restrict__ Wih,
    const float* __restrict__ xs, const float* __restrict__ Wzh,
    const float* __restrict__ bvec)
{
    extern __shared__ float sm[];
    float* xsm   = sm;                                  // [64][65]
    float* wsm   = sm + PRE_MT * PRE_PAD;               // [128][65]
    float* svrow = sm + (PRE_MT + PRE_NT) * PRE_PAD;    // [128]

    int t  = threadIdx.x;
    int m0 = blockIdx.x * PRE_MT;
    int n0 = blockIdx.y * PRE_NT;
    int bb = m0 >> 9;   // T = 512

    {
        const float4* xg = (const float4*)(xd + (size_t)m0 * Dd);
        for (int i = t; i < PRE_MT * (Dd / 4); i += 256) {
            int row = i >> 4, dq = i & 15;
            float4 v = xg[row * 16 + dq];
            float* dst = xsm + row * PRE_PAD + dq * 4;
            dst[0] = v.x; dst[1] = v.y; dst[2] = v.z; dst[3] = v.w;
        }
    }
    {
        const float4* wg = (const float4*)(Wih + (size_t)n0 * Dd);
        for (int i = t; i < PRE_NT * (Dd / 4); i += 256) {
            int row = i >> 4, dq = i & 15;
            float4 v = wg[row * 16 + dq];
            float* dst = wsm + row * PRE_PAD + dq * 4;
            dst[0] = v.x; dst[1] = v.y; dst[2] = v.z; dst[3] = v.w;
        }
    }
    if (t < PRE_NT) {
        int gn = n0 + t;
        float acc = bvec[gn];
        const float* w = Wzh + gn * Ll;
        const float* xr = xs + bb * Ll;
#pragma unroll
        for (int l = 0; l < Ll; l++) acc += xr[l] * w[l];
        svrow[t] = acc;
    }
    __syncthreads();

    int tn = t & 15;
    int tm = t >> 4;

    float acc[4][8];
#pragma unroll
    for (int i = 0; i < 4; i++)
#pragma unroll
        for (int jj = 0; jj < 8; jj++) acc[i][jj] = 0.0f;

#pragma unroll 8
    for (int k = 0; k < Dd; k++) {
        float a[4], b[8];
#pragma unroll
        for (int i = 0; i < 4; i++)  a[i]  = xsm[(tm + 16 * i) * PRE_PAD + k];
#pragma unroll
        for (int jj = 0; jj < 8; jj++) b[jj] = wsm[(tn + 16 * jj) * PRE_PAD + k];
#pragma unroll
        for (int i = 0; i < 4; i++)
#pragma unroll
            for (int jj = 0; jj < 8; jj++) acc[i][jj] += a[i] * b[jj];
    }

    float sv[8];
#pragma unroll
    for (int jj = 0; jj < 8; jj++) sv[jj] = svrow[tn + 16 * jj];
#pragma unroll
    for (int i = 0; i < 4; i++) {
        float* orow = g_pre + (size_t)(m0 + tm + 16 * i) * G4 + n0;
#pragma unroll
        for (int jj = 0; jj < 8; jj++) orow[tn + 16 * jj] = acc[i][jj] + sv[jj];
    }
}

// ============================================================================
// Kernel 2: persistent LSTM scan — independent CTAs, 2 batch rows each.
//   R5 scalar structure, but 1024 threads with a d-SPLIT matvec:
//     low  half (tid 0..511):   j = tid,      d 0..63  (16 smem chunks)
//     high half (tid 512..1023): j = tid-512, d 64..95 (8 smem chunks)
//                                            + d 96..127 (32 registers)
//   8 warps/SMSP (vs 4) to cover FFMA-chain + LDS latency; FMA-pipe work
//   per SM unchanged.  Still exactly 2 __syncthreads() per step.
// ============================================================================
#define OFF_W    0                        // 24 chunks * 2048 = 49152 floats
#define OFF_H    (24 * 2048)              // h[2][128]
#define OFF_GL   (OFF_H + 256)            // gl[2][512]: pre + low partial
#define OFF_PH   (OFF_GL + 1024)          // ph[2][512]: high partial
#define OFF_RED  (OFF_PH + 1024)          // red[8]
#define SCAN_SMEM ((OFF_RED + 8) * 4)     // 205856 bytes

__global__ void __launch_bounds__(1024, 1)
scan_kernel(const float* __restrict__ Whh, const float* __restrict__ Wout,
            const float* __restrict__ bout, float* __restrict__ out)
{
    extern __shared__ float sm[];
    int tid = threadIdx.x;
    int b0  = blockIdx.x * 2;
    int j   = tid & 511;            // gate-column index 0..511
    bool hi = tid >= 512;           // warp-uniform

    // ---- W into smem chunks: Wv[c][j][q] = W_hh[j][4c+q]
    //      low loads c 0..15 (d 0..63), high loads c 16..23 (d 64..95)
    if (!hi) {
#pragma unroll 4
        for (int c = 0; c < 16; c++) {
            float4 v = *(const float4*)(Whh + (size_t)j * 128 + c * 4);
            float* dst = sm + OFF_W + c * 2048 + j * 4;
            dst[0] = v.x; dst[1] = v.y; dst[2] = v.z; dst[3] = v.w;
        }
    } else {
#pragma unroll 4
        for (int c = 16; c < 24; c++) {
            float4 v = *(const float4*)(Whh + (size_t)j * 128 + c * 4);
            float* dst = sm + OFF_W + c * 2048 + j * 4;
            dst[0] = v.x; dst[1] = v.y; dst[2] = v.z; dst[3] = v.w;
        }
    }
    // ---- high half: W d 96..127 into 32 scalar registers
    float wr[32];
    if (hi) {
        const float* ws = Whh + (size_t)j * 128 + 96;
#pragma unroll
        for (int c = 0; c < 8; c++) {
            float4 v = *(const float4*)(ws + c * 4);
            wr[4 * c + 0] = v.x; wr[4 * c + 1] = v.y;
            wr[4 * c + 2] = v.z; wr[4 * c + 3] = v.w;
        }
    }
    if (tid < 256) sm[OFF_H + tid] = 0.0f;
    __syncthreads();

    int r2 = tid >> 7;        // row 0..1 (update role, tid < 256)
    int k  = tid & 127;       // hidden index (update role)

    float cst = 0.0f;
    float wo  = (tid < 256) ? Wout[k] : 0.0f;
    float bo  = bout[0];

    const float* pre0 = g_pre + ((size_t)(b0 + 0) * Tt) * G4 + j;
    const float* pre1 = g_pre + ((size_t)(b0 + 1) * Tt) * G4 + j;
    const float* hsh  = sm + OFF_H;

    for (int t = 0; t < Tt; t++) {
        float acc0 = 0.0f, acc1 = 0.0f;

        if (!hi) {
            // prefetch pre values (only the low half assembles gl)
            float p0 = pre0[(size_t)t * G4];
            float p1 = pre1[(size_t)t * G4];
            // d 0..63 from smem
#pragma unroll
            for (int c = 0; c < 16; c++) {
                float4 w  = *(const float4*)(sm + OFF_W + c * 2048 + j * 4);
                float4 h0 = *(const float4*)(hsh + 0 * 128 + c * 4);
                float4 h1 = *(const float4*)(hsh + 1 * 128 + c * 4);
                acc0 += w.x * h0.x + w.y * h0.y + w.z * h0.z + w.w * h0.w;
                acc1 += w.x * h1.x + w.y * h1.y + w.z * h1.z + w.w * h1.w;
            }
            sm[OFF_GL + 0 * 512 + j] = p0 + acc0;
            sm[OFF_GL + 1 * 512 + j] = p1 + acc1;
        } else {
            // d 64..95 from smem
#pragma unroll
            for (int c = 16; c < 24; c++) {
                float4 w  = *(const float4*)(sm + OFF_W + c * 2048 + j * 4);
                float4 h0 = *(const float4*)(hsh + 0 * 128 + c * 4);
                float4 h1 = *(const float4*)(hsh + 1 * 128 + c * 4);
                acc0 += w.x * h0.x + w.y * h0.y + w.z * h0.z + w.w * h0.w;
                acc1 += w.x * h1.x + w.y * h1.y + w.z * h1.z + w.w * h1.w;
            }
            // d 96..127 from registers
#pragma unroll
            for (int c = 0; c < 8; c++) {
                float4 h0 = *(const float4*)(hsh + 0 * 128 + 96 + c * 4);
                float4 h1 = *(const float4*)(hsh + 1 * 128 + 96 + c * 4);
                acc0 += wr[4*c] * h0.x + wr[4*c+1] * h0.y + wr[4*c+2] * h0.z + wr[4*c+3] * h0.w;
                acc1 += wr[4*c] * h1.x + wr[4*c+1] * h1.y + wr[4*c+2] * h1.z + wr[4*c+3] * h1.w;
            }
            sm[OFF_PH + 0 * 512 + j] = acc0;
            sm[OFF_PH + 1 * 512 + j] = acc1;
        }
        __syncthreads();   // partials + gl visible

        // state update (threads 0..255: 2 rows x 128 hidden)
        if (tid < 256) {
            int gb = r2 * 512 + k;
            float gi = sm[OFF_GL + gb]       + sm[OFF_PH + gb];
            float gf = sm[OFF_GL + gb + 128] + sm[OFF_PH + gb + 128];
            float gc = sm[OFF_GL + gb + 256] + sm[OFF_PH + gb + 256];
            float go = sm[OFF_GL + gb + 384] + sm[OFF_PH + gb + 384];
            cst = sigf(gf) * cst + sigf(gi) * tanhf_fast(gc);
            float hval = sigf(go) * tanhf_fast(cst);
            sm[OFF_H + r2 * 128 + k] = hval;

            // fused O=1 head: warp-reduce hval*wo (warps 0..7)
            float v = hval * wo;
            v += __shfl_down_sync(0xffffffffu, v, 16);
            v += __shfl_down_sync(0xffffffffu, v, 8);
            v += __shfl_down_sync(0xffffffffu, v, 4);
            v += __shfl_down_sync(0xffffffffu, v, 2);
            v += __shfl_down_sync(0xffffffffu, v, 1);
            if ((tid & 31) == 0) sm[OFF_RED + (tid >> 5)] = v;
        }
        __syncthreads();   // h + red ready for next step

        if (tid < 2) {
            const float* rd = sm + OFF_RED + tid * 4;
            out[(size_t)(b0 + tid) * Tt + t] = rd[0] + rd[1] + rd[2] + rd[3] + bo;
        }
    }
}

// ============================================================================
// launch
// ============================================================================
extern "C" void kernel_launch(void* const* d_in, const int* in_sizes, int n_in,
                              void* d_out, int out_size)
{
    const float* x_dyn = (const float*)d_in[0];
    const float* x_sta = (const float*)d_in[1];
    const float* W_ih  = (const float*)d_in[2];
    const float* W_hh  = (const float*)d_in[3];
    const float* W_zh  = (const float*)d_in[4];
    const float* bvec  = (const float*)d_in[5];
    const float* W_out = (const float*)d_in[6];
    const float* b_out = (const float*)d_in[7];
    float* out = (float*)d_out;

    (void)in_sizes; (void)n_in; (void)out_size;

    cudaFuncSetAttribute(pre_kernel,
                         cudaFuncAttributeMaxDynamicSharedMemorySize, PRE_SMEM);
    cudaFuncSetAttribute(scan_kernel,
                         cudaFuncAttributeMaxDynamicSharedMemorySize, SCAN_SMEM);

    dim3 pre_grid((Bb * Tt) / PRE_MT, G4 / PRE_NT);   // 2048 x 4
    pre_kernel<<<pre_grid, 256, PRE_SMEM>>>(x_dyn, W_ih, x_sta, W_zh, bvec);

    scan_kernel<<<128, 1024, SCAN_SMEM>>>(W_hh, W_out, b_out, out);
}

// round 8
// speedup vs baseline: 1.1942x; 1.1942x over previous
#include <cuda_runtime.h>
#include <cstdint>
#include <cstddef>

// Problem dims (fixed by reference)
#define Bb 256
#define Tt 512
#define Dd 64
#define Ll 32
#define Hh 128
#define G4 512   // 4*H

// ---------------- scratch (device globals; no allocation allowed) ----------
__device__ float g_pre[(size_t)Bb * Tt * G4];   // 268 MB: pre-activations

// ---------------- math helpers ---------------------------------------------
__device__ __forceinline__ float sigf(float x) {
    return __fdividef(1.0f, 1.0f + __expf(-x));
}
__device__ __forceinline__ float tanhf_fast(float x) {
    x = fminf(20.0f, fmaxf(-20.0f, x));
    float e = __expf(-2.0f * x);
    return __fdividef(1.0f - e, 1.0f + e);
}

// ============================================================================
// Kernel 1: pre-GEMM with fused static part (R5 body, unchanged — proven).
// ============================================================================
#define PRE_MT 64
#define PRE_NT 128
#define PRE_PAD 65
#define PRE_SMEM (((PRE_MT + PRE_NT) * PRE_PAD + PRE_NT) * 4)   // 50432 bytes

__global__ __launch_bounds__(256) void pre_kernel(
    const float* __restrict__ xd, const float* __restrict__ Wih,
    const float* __restrict__ xs, const float* __restrict__ Wzh,
    const float* __restrict__ bvec)
{
    extern __shared__ float sm[];
    float* xsm   = sm;                                  // [64][65]
    float* wsm   = sm + PRE_MT * PRE_PAD;               // [128][65]
    float* svrow = sm + (PRE_MT + PRE_NT) * PRE_PAD;    // [128]

    int t  = threadIdx.x;
    int m0 = blockIdx.x * PRE_MT;
    int n0 = blockIdx.y * PRE_NT;
    int bb = m0 >> 9;   // T = 512

    {
        const float4* xg = (const float4*)(xd + (size_t)m0 * Dd);
        for (int i = t; i < PRE_MT * (Dd / 4); i += 256) {
            int row = i >> 4, dq = i & 15;
            float4 v = xg[row * 16 + dq];
            float* dst = xsm + row * PRE_PAD + dq * 4;
            dst[0] = v.x; dst[1] = v.y; dst[2] = v.z; dst[3] = v.w;
        }
    }
    {
        const float4* wg = (const float4*)(Wih + (size_t)n0 * Dd);
        for (int i = t; i < PRE_NT * (Dd / 4); i += 256) {
            int row = i >> 4, dq = i & 15;
            float4 v = wg[row * 16 + dq];
            float* dst = wsm + row * PRE_PAD + dq * 4;
            dst[0] = v.x; dst[1] = v.y; dst[2] = v.z; dst[3] = v.w;
        }
    }
    if (t < PRE_NT) {
        int gn = n0 + t;
        float acc = bvec[gn];
        const float* w = Wzh + gn * Ll;
        const float* xr = xs + bb * Ll;
#pragma unroll
        for (int l = 0; l < Ll; l++) acc += xr[l] * w[l];
        svrow[t] = acc;
    }
    __syncthreads();

    int tn = t & 15;
    int tm = t >> 4;

    float acc[4][8];
#pragma unroll
    for (int i = 0; i < 4; i++)
#pragma unroll
        for (int jj = 0; jj < 8; jj++) acc[i][jj] = 0.0f;

#pragma unroll 8
    for (int k = 0; k < Dd; k++) {
        float a[4], b[8];
#pragma unroll
        for (int i = 0; i < 4; i++)  a[i]  = xsm[(tm + 16 * i) * PRE_PAD + k];
#pragma unroll
        for (int jj = 0; jj < 8; jj++) b[jj] = wsm[(tn + 16 * jj) * PRE_PAD + k];
#pragma unroll
        for (int i = 0; i < 4; i++)
#pragma unroll
            for (int jj = 0; jj < 8; jj++) acc[i][jj] += a[i] * b[jj];
    }

    float sv[8];
#pragma unroll
    for (int jj = 0; jj < 8; jj++) sv[jj] = svrow[tn + 16 * jj];
#pragma unroll
    for (int i = 0; i < 4; i++) {
        float* orow = g_pre + (size_t)(m0 + tm + 16 * i) * G4 + n0;
#pragma unroll
        for (int jj = 0; jj < 8; jj++) orow[tn + 16 * jj] = acc[i][jj] + sv[jj];
    }
}

// ============================================================================
// Kernel 2: persistent LSTM scan — EXACT R5 structure (the 1462us winner:
//   independent CTAs, 512 threads, 2 batch rows, scalar FFMA) plus three
//   latency-targeted edits:
//   (1) 4 independent FFMA chains (even/odd chunks per row)
//   (2) gate activations computed by all 512 matvec threads (warp-uniform)
//   (3) next-step pre prefetched during the update phase
// ============================================================================
#define NCH 24   // smem W chunks of 4 d-values (d 0..95)
#define OFF_W    0                        // 24 * 512 * 4 floats (192KB)
#define OFF_H    (NCH * 2048)             // h[2][128]
#define OFF_G    (OFF_H + 256)            // act[2][512]
#define OFF_RED  (OFF_G + 1024)           // red[8]
#define SCAN_SMEM ((OFF_RED + 8) * 4)     // 201760 bytes

__global__ void __launch_bounds__(512, 1)
scan_kernel(const float* __restrict__ Whh, const float* __restrict__ Wout,
            const float* __restrict__ bout, float* __restrict__ out)
{
    extern __shared__ float sm[];
    int tid = threadIdx.x;
    int b0  = blockIdx.x * 2;
    int j   = tid;                        // gate-column index 0..511
    bool is_tanh_gate = ((j >> 7) == 2);  // warp-uniform

    // ---- W d 0..95 into smem: Wv[c][j][q] = W_hh[j][4c+q]
#pragma unroll 4
    for (int c = 0; c < NCH; c++) {
        float4 v = *(const float4*)(Whh + (size_t)j * 128 + c * 4);
        float* dst = sm + OFF_W + c * 2048 + j * 4;
        dst[0] = v.x; dst[1] = v.y; dst[2] = v.z; dst[3] = v.w;
    }
    // ---- W d 96..127 into 32 scalar registers
    float wr[32];
    {
        const float* ws = Whh + (size_t)j * 128 + 96;
#pragma unroll
        for (int c = 0; c < 8; c++) {
            float4 v = *(const float4*)(ws + c * 4);
            wr[4 * c + 0] = v.x; wr[4 * c + 1] = v.y;
            wr[4 * c + 2] = v.z; wr[4 * c + 3] = v.w;
        }
    }
    if (tid < 256) sm[OFF_H + tid] = 0.0f;
    __syncthreads();

    int r2 = tid >> 7;        // row 0..1 (update role, tid < 256)
    int k  = tid & 127;       // hidden index (update role)

    float cst = 0.0f;
    float wo  = (tid < 256) ? Wout[k] : 0.0f;
    float bo  = bout[0];

    const float* pre0 = g_pre + ((size_t)(b0 + 0) * Tt) * G4 + j;
    const float* pre1 = g_pre + ((size_t)(b0 + 1) * Tt) * G4 + j;
    const float* hsh  = sm + OFF_H;

    // prefetch pre for t=0
    float p0 = pre0[0];
    float p1 = pre1[0];

    for (int t = 0; t < Tt; t++) {
        // full matvec, 4 independent FFMA chains (even/odd chunks per row)
        float a0e = 0.0f, a0o = 0.0f, a1e = 0.0f, a1o = 0.0f;
#pragma unroll
        for (int c = 0; c < NCH; c += 2) {       // d 0..95 (smem weights)
            float4 we  = *(const float4*)(sm + OFF_W + c * 2048 + j * 4);
            float4 h0e = *(const float4*)(hsh + 0 * 128 + c * 4);
            float4 h1e = *(const float4*)(hsh + 1 * 128 + c * 4);
            a0e += we.x * h0e.x + we.y * h0e.y + we.z * h0e.z + we.w * h0e.w;
            a1e += we.x * h1e.x + we.y * h1e.y + we.z * h1e.z + we.w * h1e.w;
            float4 wo4 = *(const float4*)(sm + OFF_W + (c + 1) * 2048 + j * 4);
            float4 h0o = *(const float4*)(hsh + 0 * 128 + (c + 1) * 4);
            float4 h1o = *(const float4*)(hsh + 1 * 128 + (c + 1) * 4);
            a0o += wo4.x * h0o.x + wo4.y * h0o.y + wo4.z * h0o.z + wo4.w * h0o.w;
            a1o += wo4.x * h1o.x + wo4.y * h1o.y + wo4.z * h1o.z + wo4.w * h1o.w;
        }
#pragma unroll
        for (int c = 0; c < 8; c += 2) {         // d 96..127 (register weights)
            float4 h0e = *(const float4*)(hsh + 0 * 128 + 96 + c * 4);
            float4 h1e = *(const float4*)(hsh + 1 * 128 + 96 + c * 4);
            a0e += wr[4*c] * h0e.x + wr[4*c+1] * h0e.y + wr[4*c+2] * h0e.z + wr[4*c+3] * h0e.w;
            a1e += wr[4*c] * h1e.x + wr[4*c+1] * h1e.y + wr[4*c+2] * h1e.z + wr[4*c+3] * h1e.w;
            float4 h0o = *(const float4*)(hsh + 0 * 128 + 96 + (c + 1) * 4);
            float4 h1o = *(const float4*)(hsh + 1 * 128 + 96 + (c + 1) * 4);
            a0o += wr[4*c+4] * h0o.x + wr[4*c+5] * h0o.y + wr[4*c+6] * h0o.z + wr[4*c+7] * h0o.w;
            a1o += wr[4*c+4] * h1o.x + wr[4*c+5] * h1o.y + wr[4*c+6] * h1o.z + wr[4*c+7] * h1o.w;
        }
        float g0 = p0 + (a0e + a0o);
        float g1 = p1 + (a1e + a1o);

        // gate activation here (all 512 threads; warp-uniform branch)
        float act0, act1;
        if (is_tanh_gate) { act0 = tanhf_fast(g0); act1 = tanhf_fast(g1); }
        else              { act0 = sigf(g0);       act1 = sigf(g1);       }
        sm[OFF_G + 0 * 512 + j] = act0;
        sm[OFF_G + 1 * 512 + j] = act1;

        // prefetch next step's pre (hides LDG under barrier + update)
        {
            int tn_ = (t + 1 < Tt) ? (t + 1) : (Tt - 1);
            p0 = pre0[(size_t)tn_ * G4];
            p1 = pre1[(size_t)tn_ * G4];
        }
        __syncthreads();   // activations visible

        // state update (threads 0..255: 2 rows x 128 hidden)
        if (tid < 256) {
            float ai = sm[OFF_G + r2 * 512 + k];
            float af = sm[OFF_G + r2 * 512 + 128 + k];
            float ag = sm[OFF_G + r2 * 512 + 256 + k];
            float ao = sm[OFF_G + r2 * 512 + 384 + k];
            cst = af * cst + ai * ag;
            float hval = ao * tanhf_fast(cst);
            sm[OFF_H + r2 * 128 + k] = hval;

            // fused O=1 head: warp-reduce hval*wo (warps 0..7)
            float v = hval * wo;
            v += __shfl_down_sync(0xffffffffu, v, 16);
            v += __shfl_down_sync(0xffffffffu, v, 8);
            v += __shfl_down_sync(0xffffffffu, v, 4);
            v += __shfl_down_sync(0xffffffffu, v, 2);
            v += __shfl_down_sync(0xffffffffu, v, 1);
            if ((tid & 31) == 0) sm[OFF_RED + (tid >> 5)] = v;
        }
        __syncthreads();   // h + red ready; also fences act[] overwrite

        if (tid < 2) {
            const float* rd = sm + OFF_RED + tid * 4;
            out[(size_t)(b0 + tid) * Tt + t] = rd[0] + rd[1] + rd[2] + rd[3] + bo;
        }
    }
}

// ============================================================================
// launch
// ============================================================================
extern "C" void kernel_launch(void* const* d_in, const int* in_sizes, int n_in,
                              void* d_out, int out_size)
{
    const float* x_dyn = (const float*)d_in[0];
    const float* x_sta = (const float*)d_in[1];
    const float* W_ih  = (const float*)d_in[2];
    const float* W_hh  = (const float*)d_in[3];
    const float* W_zh  = (const float*)d_in[4];
    const float* bvec  = (const float*)d_in[5];
    const float* W_out = (const float*)d_in[6];
    const float* b_out = (const float*)d_in[7];
    float* out = (float*)d_out;

    (void)in_sizes; (void)n_in; (void)out_size;

    cudaFuncSetAttribute(pre_kernel,
                         cudaFuncAttributeMaxDynamicSharedMemorySize, PRE_SMEM);
    cudaFuncSetAttribute(scan_kernel,
                         cudaFuncAttributeMaxDynamicSharedMemorySize, SCAN_SMEM);

    dim3 pre_grid((Bb * Tt) / PRE_MT, G4 / PRE_NT);   // 2048 x 4
    pre_kernel<<<pre_grid, 256, PRE_SMEM>>>(x_dyn, W_ih, x_sta, W_zh, bvec);

    scan_kernel<<<128, 512, SCAN_SMEM>>>(W_hh, W_out, b_out, out);
}

// round 9
// speedup vs baseline: 1.3559x; 1.1355x over previous
#include <cuda_runtime.h>
#include <cuda_fp16.h>
#include <cstdint>
#include <cstddef>

// Problem dims (fixed by reference)
#define Bb 256
#define Tt 512
#define Dd 64
#define Ll 32
#define Hh 128
#define G4 512   // 4*H

// ---------------- scratch (device globals; no allocation allowed) ----------
__device__ float g_pre[(size_t)Bb * Tt * G4];   // 268 MB: pre-activations

// ---------------- math helpers ---------------------------------------------
__device__ __forceinline__ float sigf(float x) {
    return __fdividef(1.0f, 1.0f + __expf(-x));
}
__device__ __forceinline__ float tanhf_fast(float x) {
    x = fminf(20.0f, fmaxf(-20.0f, x));
    float e = __expf(-2.0f * x);
    return __fdividef(1.0f - e, 1.0f + e);
}

// ============================================================================
// Kernel 1: pre-GEMM with fused static part (unchanged — proven).
// ============================================================================
#define PRE_MT 64
#define PRE_NT 128
#define PRE_PAD 65
#define PRE_SMEM (((PRE_MT + PRE_NT) * PRE_PAD + PRE_NT) * 4)   // 50432 bytes

__global__ __launch_bounds__(256) void pre_kernel(
    const float* __restrict__ xd, const float* __restrict__ Wih,
    const float* __restrict__ xs, const float* __restrict__ Wzh,
    const float* __restrict__ bvec)
{
    extern __shared__ float sm[];
    float* xsm   = sm;                                  // [64][65]
    float* wsm   = sm + PRE_MT * PRE_PAD;               // [128][65]
    float* svrow = sm + (PRE_MT + PRE_NT) * PRE_PAD;    // [128]

    int t  = threadIdx.x;
    int m0 = blockIdx.x * PRE_MT;
    int n0 = blockIdx.y * PRE_NT;
    int bb = m0 >> 9;   // T = 512

    {
        const float4* xg = (const float4*)(xd + (size_t)m0 * Dd);
        for (int i = t; i < PRE_MT * (Dd / 4); i += 256) {
            int row = i >> 4, dq = i & 15;
            float4 v = xg[row * 16 + dq];
            float* dst = xsm + row * PRE_PAD + dq * 4;
            dst[0] = v.x; dst[1] = v.y; dst[2] = v.z; dst[3] = v.w;
        }
    }
    {
        const float4* wg = (const float4*)(Wih + (size_t)n0 * Dd);
        for (int i = t; i < PRE_NT * (Dd / 4); i += 256) {
            int row = i >> 4, dq = i & 15;
            float4 v = wg[row * 16 + dq];
            float* dst = wsm + row * PRE_PAD + dq * 4;
            dst[0] = v.x; dst[1] = v.y; dst[2] = v.z; dst[3] = v.w;
        }
    }
    if (t < PRE_NT) {
        int gn = n0 + t;
        float acc = bvec[gn];
        const float* w = Wzh + gn * Ll;
        const float* xr = xs + bb * Ll;
#pragma unroll
        for (int l = 0; l < Ll; l++) acc += xr[l] * w[l];
        svrow[t] = acc;
    }
    __syncthreads();

    int tn = t & 15;
    int tm = t >> 4;

    float acc[4][8];
#pragma unroll
    for (int i = 0; i < 4; i++)
#pragma unroll
        for (int jj = 0; jj < 8; jj++) acc[i][jj] = 0.0f;

#pragma unroll 8
    for (int k = 0; k < Dd; k++) {
        float a[4], b[8];
#pragma unroll
        for (int i = 0; i < 4; i++)  a[i]  = xsm[(tm + 16 * i) * PRE_PAD + k];
#pragma unroll
        for (int jj = 0; jj < 8; jj++) b[jj] = wsm[(tn + 16 * jj) * PRE_PAD + k];
#pragma unroll
        for (int i = 0; i < 4; i++)
#pragma unroll
            for (int jj = 0; jj < 8; jj++) acc[i][jj] += a[i] * b[jj];
    }

    float sv[8];
#pragma unroll
    for (int jj = 0; jj < 8; jj++) sv[jj] = svrow[tn + 16 * jj];
#pragma unroll
    for (int i = 0; i < 4; i++) {
        float* orow = g_pre + (size_t)(m0 + tm + 16 * i) * G4 + n0;
#pragma unroll
        for (int jj = 0; jj < 8; jj++) orow[tn + 16 * jj] = acc[i][jj] + sv[jj];
    }
}

// ============================================================================
// Kernel 2: persistent LSTM scan — EXACT R4 structure (the 1462us winner:
//   independent CTAs, 512 threads, 2 batch rows, scalar FFMA, activations in
//   the update phase) with ONE change: W_hh d 0..95 stored as fp16 in smem
//   (halves the dominant W crossbar term 1536 -> 768 cyc/step; cvt lands on
//   the idle ALU pipe).  d 96..127 remain exact fp32 in registers.
//   fp16 weight rounding (2^-11) -> final rel_err ~1e-4, within 1e-3.
// ============================================================================
#define NWCH 12   // fp16 W chunks of 8 d-values (d 0..95)
// float-index offsets within dynamic smem
#define OFF_WH   0                        // 12 * 512 * 8 halfs = 24576 floats
#define OFF_H    24576                    // h[2][128]
#define OFF_G    (OFF_H + 256)            // g[2][512]
#define OFF_RED  (OFF_G + 1024)           // red[8]
#define SCAN_SMEM ((OFF_RED + 8) * 4)     // 103456 bytes

__global__ void __launch_bounds__(512, 1)
scan_kernel(const float* __restrict__ Whh, const float* __restrict__ Wout,
            const float* __restrict__ bout, float* __restrict__ out)
{
    extern __shared__ float sm[];
    __half* whsm = (__half*)(sm + OFF_WH);   // [12 chunks][512 j][8 d] fp16
    int tid = threadIdx.x;
    int b0  = blockIdx.x * 2;
    int j   = tid;                 // gate-column index 0..511

    // ---- W d 0..95 -> fp16 smem: whsm[c][j][0..7] = half(W_hh[j][8c..8c+7])
#pragma unroll
    for (int c = 0; c < NWCH; c++) {
        float4 va = *(const float4*)(Whh + (size_t)j * 128 + c * 8);
        float4 vb = *(const float4*)(Whh + (size_t)j * 128 + c * 8 + 4);
        __half2 p0 = __floats2half2_rn(va.x, va.y);
        __half2 p1 = __floats2half2_rn(va.z, va.w);
        __half2 p2 = __floats2half2_rn(vb.x, vb.y);
        __half2 p3 = __floats2half2_rn(vb.z, vb.w);
        uint4 pk;
        pk.x = *(uint32_t*)&p0; pk.y = *(uint32_t*)&p1;
        pk.z = *(uint32_t*)&p2; pk.w = *(uint32_t*)&p3;
        *(uint4*)(whsm + (size_t)c * 4096 + j * 8) = pk;
    }
    // ---- W d 96..127 into 32 scalar fp32 registers (exact)
    float wr[32];
    {
        const float* ws = Whh + (size_t)j * 128 + 96;
#pragma unroll
        for (int c = 0; c < 8; c++) {
            float4 v = *(const float4*)(ws + c * 4);
            wr[4 * c + 0] = v.x; wr[4 * c + 1] = v.y;
            wr[4 * c + 2] = v.z; wr[4 * c + 3] = v.w;
        }
    }
    if (tid < 256) sm[OFF_H + tid] = 0.0f;
    __syncthreads();

    int r2 = tid >> 7;        // row 0..1 (update role, tid < 256)
    int k  = tid & 127;       // hidden index (update role)

    float cst = 0.0f;
    float wo  = (tid < 256) ? Wout[k] : 0.0f;
    float bo  = bout[0];

    const float* pre0 = g_pre + ((size_t)(b0 + 0) * Tt) * G4 + j;
    const float* pre1 = g_pre + ((size_t)(b0 + 1) * Tt) * G4 + j;
    const float* hsh  = sm + OFF_H;

    for (int t = 0; t < Tt; t++) {
        float p0 = pre0[(size_t)t * G4];
        float p1 = pre1[(size_t)t * G4];

        // full matvec: acc_r = sum_d W[j][d] * h[r][d]
        float acc0 = 0.0f, acc1 = 0.0f;
#pragma unroll
        for (int c = 0; c < NWCH; c++) {         // d 0..95 (fp16 smem weights)
            uint4 pk = *(const uint4*)(whsm + (size_t)c * 4096 + j * 8);
            float2 w0 = __half22float2(*(__half2*)&pk.x);   // d 8c+0,1
            float2 w1 = __half22float2(*(__half2*)&pk.y);   // d 8c+2,3
            float2 w2 = __half22float2(*(__half2*)&pk.z);   // d 8c+4,5
            float2 w3 = __half22float2(*(__half2*)&pk.w);   // d 8c+6,7
            float4 h0a = *(const float4*)(hsh + 0 * 128 + c * 8);
            float4 h0b = *(const float4*)(hsh + 0 * 128 + c * 8 + 4);
            float4 h1a = *(const float4*)(hsh + 1 * 128 + c * 8);
            float4 h1b = *(const float4*)(hsh + 1 * 128 + c * 8 + 4);
            acc0 += w0.x * h0a.x + w0.y * h0a.y + w1.x * h0a.z + w1.y * h0a.w
                  + w2.x * h0b.x + w2.y * h0b.y + w3.x * h0b.z + w3.y * h0b.w;
            acc1 += w0.x * h1a.x + w0.y * h1a.y + w1.x * h1a.z + w1.y * h1a.w
                  + w2.x * h1b.x + w2.y * h1b.y + w3.x * h1b.z + w3.y * h1b.w;
        }
#pragma unroll
        for (int c = 0; c < 8; c++) {            // d 96..127 (fp32 registers)
            float4 h0 = *(const float4*)(hsh + 0 * 128 + 96 + c * 4);
            float4 h1 = *(const float4*)(hsh + 1 * 128 + 96 + c * 4);
            acc0 += wr[4*c] * h0.x + wr[4*c+1] * h0.y + wr[4*c+2] * h0.z + wr[4*c+3] * h0.w;
            acc1 += wr[4*c] * h1.x + wr[4*c+1] * h1.y + wr[4*c+2] * h1.z + wr[4*c+3] * h1.w;
        }

        // stage full gate pre-activations
        sm[OFF_G + 0 * 512 + j] = p0 + acc0;
        sm[OFF_G + 1 * 512 + j] = p1 + acc1;
        __syncthreads();

        // state update (threads 0..255: 2 rows x 128 hidden)
        if (tid < 256) {
            float gi = sm[OFF_G + r2 * 512 + k];
            float gf = sm[OFF_G + r2 * 512 + 128 + k];
            float gc = sm[OFF_G + r2 * 512 + 256 + k];
            float go = sm[OFF_G + r2 * 512 + 384 + k];
            cst = sigf(gf) * cst + sigf(gi) * tanhf_fast(gc);
            float hval = sigf(go) * tanhf_fast(cst);
            sm[OFF_H + r2 * 128 + k] = hval;

            // fused O=1 head: warp-reduce hval*wo (warps 0..7)
            float v = hval * wo;
            v += __shfl_down_sync(0xffffffffu, v, 16);
            v += __shfl_down_sync(0xffffffffu, v, 8);
            v += __shfl_down_sync(0xffffffffu, v, 4);
            v += __shfl_down_sync(0xffffffffu, v, 2);
            v += __shfl_down_sync(0xffffffffu, v, 1);
            if ((tid & 31) == 0) sm[OFF_RED + (tid >> 5)] = v;
        }
        __syncthreads();   // h + red ready for next step

        if (tid < 2) {
            const float* rd = sm + OFF_RED + tid * 4;
            out[(size_t)(b0 + tid) * Tt + t] = rd[0] + rd[1] + rd[2] + rd[3] + bo;
        }
    }
}

// ============================================================================
// launch
// ============================================================================
extern "C" void kernel_launch(void* const* d_in, const int* in_sizes, int n_in,
                              void* d_out, int out_size)
{
    const float* x_dyn = (const float*)d_in[0];
    const float* x_sta = (const float*)d_in[1];
    const float* W_ih  = (const float*)d_in[2];
    const float* W_hh  = (const float*)d_in[3];
    const float* W_zh  = (const float*)d_in[4];
    const float* bvec  = (const float*)d_in[5];
    const float* W_out = (const float*)d_in[6];
    const float* b_out = (const float*)d_in[7];
    float* out = (float*)d_out;

    (void)in_sizes; (void)n_in; (void)out_size;

    cudaFuncSetAttribute(pre_kernel,
                         cudaFuncAttributeMaxDynamicSharedMemorySize, PRE_SMEM);
    cudaFuncSetAttribute(scan_kernel,
                         cudaFuncAttributeMaxDynamicSharedMemorySize, SCAN_SMEM);

    dim3 pre_grid((Bb * Tt) / PRE_MT, G4 / PRE_NT);   // 2048 x 4
    pre_kernel<<<pre_grid, 256, PRE_SMEM>>>(x_dyn, W_ih, x_sta, W_zh, bvec);

    scan_kernel<<<128, 512, SCAN_SMEM>>>(W_hh, W_out, b_out, out);
}